// round 2
// baseline (speedup 1.0000x reference)
#include <cuda_runtime.h>
#include <cstdint>

#define N_ROWS 16384
#define NC 64
#define BM 128
#define BK 32
#define KSPLIT 8
#define KCHUNK (N_ROWS / KSPLIT)   /* 2048 */
#define NIT (KCHUNK / BK)          /* 64   */
#define AS 36                      /* A smem row stride (floats), conflict-free */
#define BS 72                      /* B smem row stride (floats), conflict-free */
#define A_STG (BM * AS)            /* 4608 floats */
#define B_STG (BK * BS)            /* 2304 floats */
#define STAGES 3
#define SMEM_BYTES (STAGES * (A_STG + B_STG) * 4) /* 82944 B */

// Scratch (allocation-free rule: __device__ globals)
__device__ float g_B[N_ROWS * NC];                 // x @ w, tf32-rounded (4 MiB)
__device__ float g_partial[KSPLIT][N_ROWS * NC];   // K-split partials (32 MiB)

// ---------------------------------------------------------------------------
// helpers
// ---------------------------------------------------------------------------
__device__ __forceinline__ uint32_t cvt_rna_tf32(float f) {
    uint32_t r;
    asm("cvt.rna.tf32.f32 %0, %1;" : "=r"(r) : "f"(f));
    return r;
}

__device__ __forceinline__ void mma_tf32(float c[4],
                                         uint32_t a0, uint32_t a1, uint32_t a2, uint32_t a3,
                                         uint32_t b0, uint32_t b1) {
    asm volatile(
        "mma.sync.aligned.m16n8k8.row.col.f32.tf32.tf32.f32 "
        "{%0,%1,%2,%3},{%4,%5,%6,%7},{%8,%9},{%0,%1,%2,%3};"
        : "+f"(c[0]), "+f"(c[1]), "+f"(c[2]), "+f"(c[3])
        : "r"(a0), "r"(a1), "r"(a2), "r"(a3), "r"(b0), "r"(b1));
}

__device__ __forceinline__ void cp_async16(const float* s, const float* g) {
    uint32_t sa = (uint32_t)__cvta_generic_to_shared((void*)s);
    asm volatile("cp.async.cg.shared.global [%0], [%1], 16;" :: "r"(sa), "l"(g));
}

// ---------------------------------------------------------------------------
// Kernel 1: B = rna_tf32(x @ w)   [16384,64] = [16384,64]@[64,64]
// ---------------------------------------------------------------------------
__global__ void xw_kernel(const float* __restrict__ x, const float* __restrict__ w) {
    __shared__ float ws[NC * NC];
    __shared__ float xs[16][NC];
    const int t = threadIdx.x;                 // 256 threads
    for (int i = t; i < NC * NC; i += 256) ws[i] = w[i];
    const int m0 = blockIdx.x * 16;
    for (int i = t; i < 16 * NC; i += 256) xs[i / NC][i % NC] = x[(m0 + i / NC) * NC + i % NC];
    __syncthreads();
    const int n = t & 63;
    const int r0 = t >> 6;                     // 0..3
    #pragma unroll
    for (int rr = 0; rr < 4; ++rr) {
        const int r = r0 * 4 + rr;
        float acc = 0.f;
        #pragma unroll
        for (int k = 0; k < NC; ++k) acc += xs[r][k] * ws[k * NC + n];
        g_B[(m0 + r) * NC + n] = __uint_as_float(cvt_rna_tf32(acc));
    }
}

// ---------------------------------------------------------------------------
// Kernel 2: main GEMM  partial[ks] += adj[m0:m0+128, kchunk] @ B[kchunk, :]
// 4 warps, each 32 rows (2 x m16 tiles), all 64 cols (8 x n8 tiles), tf32 mma.
// ---------------------------------------------------------------------------
__global__ void __launch_bounds__(128) gcn_main(const float* __restrict__ A) {
    extern __shared__ float smem[];
    float* sA = smem;                       // STAGES * A_STG
    float* sB = smem + STAGES * A_STG;      // STAGES * B_STG

    const int t    = threadIdx.x;
    const int bid  = blockIdx.x;
    const int m0   = (bid & 127) * BM;
    const int ks   = bid >> 7;              // 0..KSPLIT-1
    const int kbase = ks * KCHUNK;
    const int warp = t >> 5, lane = t & 31;
    const int g    = lane >> 2;             // 0..7
    const int q4   = lane & 3;              // 0..3

    float acc[2][8][4];
    #pragma unroll
    for (int i = 0; i < 2; ++i)
        #pragma unroll
        for (int j = 0; j < 8; ++j)
            #pragma unroll
            for (int c = 0; c < 4; ++c) acc[i][j][c] = 0.f;

    // ---- stage loader: A tile 128x32, B tile 32x64 ----
    auto load_stage = [&](int st, int k0) {
        float* sAs = sA + st * A_STG;
        float* sBs = sB + st * B_STG;
        #pragma unroll
        for (int j = 0; j < 8; ++j) {                 // 1024 16B-chunks of A
            const int q = j * 128 + t;
            const int row = q >> 3, seg = q & 7;
            cp_async16(sAs + row * AS + seg * 4,
                       A + (long)(m0 + row) * N_ROWS + k0 + seg * 4);
        }
        #pragma unroll
        for (int j = 0; j < 4; ++j) {                 // 512 16B-chunks of B
            const int q = j * 128 + t;
            const int row = q >> 4, seg = q & 15;
            cp_async16(sBs + row * BS + seg * 4,
                       g_B + (k0 + row) * NC + seg * 4);
        }
    };

    // prologue: fill 2 stages
    load_stage(0, kbase);
    asm volatile("cp.async.commit_group;");
    load_stage(1, kbase + BK);
    asm volatile("cp.async.commit_group;");

    for (int it = 0; it < NIT; ++it) {
        asm volatile("cp.async.wait_group 1;");
        __syncthreads();

        // issue loads for stage it+2 (buffer freed by the barrier above)
        const int nxt = it + STAGES - 1;
        if (nxt < NIT) load_stage(nxt % STAGES, kbase + nxt * BK);
        asm volatile("cp.async.commit_group;");   // empty group keeps wait cadence

        const int st = it % STAGES;
        const float* sAs = sA + st * A_STG;
        const float* sBs = sB + st * B_STG;

        #pragma unroll
        for (int kk = 0; kk < 4; ++kk) {
            const int k8 = kk * 8;
            uint32_t b0[8], b1[8];
            #pragma unroll
            for (int j = 0; j < 8; ++j) {    // conflict-free: banks 8*q4+g distinct
                b0[j] = __float_as_uint(sBs[(k8 + q4) * BS + g + 8 * j]);
                b1[j] = __float_as_uint(sBs[(k8 + q4 + 4) * BS + g + 8 * j]);
            }
            #pragma unroll
            for (int i = 0; i < 2; ++i) {
                const int R = warp * 32 + i * 16;
                // conflict-free: banks 4*g+q4 distinct
                uint32_t a0 = cvt_rna_tf32(sAs[(R + g) * AS + k8 + q4]);
                uint32_t a1 = cvt_rna_tf32(sAs[(R + g + 8) * AS + k8 + q4]);
                uint32_t a2 = cvt_rna_tf32(sAs[(R + g) * AS + k8 + q4 + 4]);
                uint32_t a3 = cvt_rna_tf32(sAs[(R + g + 8) * AS + k8 + q4 + 4]);
                #pragma unroll
                for (int j = 0; j < 8; ++j)
                    mma_tf32(acc[i][j], a0, a1, a2, a3, b0[j], b1[j]);
            }
        }
    }

    // epilogue: unique (ks,m,n) per thread-value -> plain stores, deterministic
    float* P = &g_partial[ks][0];
    #pragma unroll
    for (int i = 0; i < 2; ++i) {
        #pragma unroll
        for (int j = 0; j < 8; ++j) {
            const int row = m0 + warp * 32 + i * 16 + g;
            const int col = j * 8 + q4 * 2;
            *(float2*)(P + (long)row * NC + col)       = make_float2(acc[i][j][0], acc[i][j][1]);
            *(float2*)(P + (long)(row + 8) * NC + col) = make_float2(acc[i][j][2], acc[i][j][3]);
        }
    }
}

// ---------------------------------------------------------------------------
// Kernel 3: out = sum_k partial[k]
// ---------------------------------------------------------------------------
__global__ void reduce_k(float* __restrict__ out) {
    const int idx = blockIdx.x * blockDim.x + threadIdx.x;   // float4 index
    float4 s = make_float4(0.f, 0.f, 0.f, 0.f);
    #pragma unroll
    for (int k = 0; k < KSPLIT; ++k) {
        const float4 v = ((const float4*)g_partial[k])[idx];
        s.x += v.x; s.y += v.y; s.z += v.z; s.w += v.w;
    }
    ((float4*)out)[idx] = s;
}

// ---------------------------------------------------------------------------
extern "C" void kernel_launch(void* const* d_in, const int* in_sizes, int n_in,
                              void* d_out, int out_size) {
    const float* x   = (const float*)d_in[0];   // [16384,64]
    const float* adj = (const float*)d_in[1];   // [16384,16384]
    const float* w   = (const float*)d_in[2];   // [64,64]
    float* out = (float*)d_out;

    cudaFuncSetAttribute(gcn_main, cudaFuncAttributeMaxDynamicSharedMemorySize, SMEM_BYTES);

    xw_kernel<<<N_ROWS / 16, 256>>>(x, w);
    gcn_main<<<128 * KSPLIT, 128, SMEM_BYTES>>>(adj);
    reduce_k<<<(N_ROWS * NC / 4) / 256, 256>>>(out);
}

// round 6
// speedup vs baseline: 1.5756x; 1.5756x over previous
#include <cuda_runtime.h>
#include <cuda_fp16.h>
#include <cstdint>

#define NROW 16384
#define NC   64
#define BM   128
#define BK   32
#define KSPLIT 8
#define KCHUNK (NROW / KSPLIT)        /* 2048 */
#define NIT    (KCHUNK / BK)          /* 64   */
#define STAGES 4

#define A_ROW_B 160                   /* 40 floats: 32 data + 8 pad  */
#define B_ROW_B 80                    /* 40 halves: 32 data + 8 pad  */
#define A_STG_B (BM * A_ROW_B)        /* 20480 */
#define B_STG_B (NC * B_ROW_B)        /*  5120 */
#define STG_B   (A_STG_B + B_STG_B)   /* 25600 */
#define MAIN_SMEM (STAGES * STG_B)    /* 102400 */

__device__ __half g_Bh[(size_t)NC * NROW];          // (x@w)^T in fp16, 2 MiB
__device__ float  g_partial[KSPLIT][NROW * NC];     // K-split partials, 32 MiB

// ---------------------------------------------------------------------------
__device__ __forceinline__ uint32_t smem_u32(const void* p) {
    uint32_t a;
    asm("{ .reg .u64 t; cvta.to.shared.u64 t, %1; cvt.u32.u64 %0, t; }" : "=r"(a) : "l"(p));
    return a;
}
__device__ __forceinline__ void cp_async16(uint32_t saddr, const void* g) {
    asm volatile("cp.async.cg.shared.global [%0], [%1], 16;" :: "r"(saddr), "l"(g));
}
__device__ __forceinline__ uint32_t pack_h2(float lo, float hi) {
    uint32_t r;
    asm("cvt.rn.f16x2.f32 %0, %1, %2;" : "=r"(r) : "f"(hi), "f"(lo));
    return r;
}
__device__ __forceinline__ void mma_f16(float c[4], uint32_t a0, uint32_t a1,
                                        uint32_t a2, uint32_t a3,
                                        uint32_t b0, uint32_t b1) {
    asm volatile(
        "mma.sync.aligned.m16n8k16.row.col.f32.f16.f16.f32 "
        "{%0,%1,%2,%3},{%4,%5,%6,%7},{%8,%9},{%0,%1,%2,%3};"
        : "+f"(c[0]), "+f"(c[1]), "+f"(c[2]), "+f"(c[3])
        : "r"(a0), "r"(a1), "r"(a2), "r"(a3), "r"(b0), "r"(b1));
}

// ---------------------------------------------------------------------------
// Kernel 1: g_Bh[n][k] = fp16( sum_c x[k][c] * w[c][n] ), 256 blocks x 64 rows
// ---------------------------------------------------------------------------
__global__ void __launch_bounds__(256) xw_t(const float* __restrict__ x,
                                            const float* __restrict__ w) {
    __shared__ float ws[NC * NC];        // 16 KB
    __shared__ float xs[64 * 65];        // 16.25 KB
    __shared__ __half ts[NC * 72];       // 9 KB  (transpose buffer)
    const int t  = threadIdx.x;
    const int k0 = blockIdx.x * 64;

    #pragma unroll
    for (int j = 0; j < 4; ++j) ((float4*)ws)[j * 256 + t] = ((const float4*)w)[j * 256 + t];
    #pragma unroll
    for (int j = 0; j < 4; ++j) {
        int i4 = j * 256 + t;
        int r = i4 >> 4, c4 = i4 & 15;
        float4 v = ((const float4*)(x + (size_t)(k0 + r) * NC))[c4];
        float* d = xs + r * 65 + c4 * 4;
        d[0] = v.x; d[1] = v.y; d[2] = v.z; d[3] = v.w;
    }
    __syncthreads();

    const int r  = t & 63;               // k-row within block
    const int n0 = (t >> 6) * 16;        // 16 output cols per thread
    float acc[16];
    #pragma unroll
    for (int j = 0; j < 16; ++j) acc[j] = 0.f;
    #pragma unroll 4
    for (int c = 0; c < NC; ++c) {
        const float xv = xs[r * 65 + c];
        #pragma unroll
        for (int j4 = 0; j4 < 4; ++j4) {
            float4 wv = *(const float4*)&ws[c * NC + n0 + j4 * 4];
            acc[j4 * 4 + 0] += xv * wv.x;
            acc[j4 * 4 + 1] += xv * wv.y;
            acc[j4 * 4 + 2] += xv * wv.z;
            acc[j4 * 4 + 3] += xv * wv.w;
        }
    }
    #pragma unroll
    for (int j = 0; j < 16; ++j) ts[(n0 + j) * 72 + r] = __float2half_rn(acc[j]);
    __syncthreads();

    // coalesced store: 512 uint4 (8 halves each), 2 per thread
    #pragma unroll
    for (int i = 0; i < 2; ++i) {
        int i4 = i * 256 + t;
        int n = i4 >> 3, c8 = i4 & 7;
        uint4 v = *(const uint4*)&ts[n * 72 + c8 * 8];
        *(uint4*)(g_Bh + (size_t)n * NROW + k0 + c8 * 8) = v;
    }
}

// ---------------------------------------------------------------------------
// Kernel 2: partial[ks][m0:m0+128,:] = adj[m0:m0+128, kchunk] @ B[kchunk,:]
// fp16 mma.sync m16n8k16, 4-stage cp.async pipeline, 2 CTAs/SM
// ---------------------------------------------------------------------------
__global__ void __launch_bounds__(128, 2) gcn_main(const float* __restrict__ A) {
    extern __shared__ char smem[];
    const uint32_t smb = smem_u32(smem);

    const int t    = threadIdx.x;
    const int bid  = blockIdx.x;
    const int m0   = (bid & 127) * BM;
    const int ks   = bid >> 7;
    const int k0   = ks * KCHUNK;
    const int warp = t >> 5, lane = t & 31;
    const int g    = lane >> 2;          // 0..7
    const int q    = lane & 3;           // 0..3

    float acc[2][8][4];
    #pragma unroll
    for (int i = 0; i < 2; ++i)
        #pragma unroll
        for (int j = 0; j < 8; ++j)
            #pragma unroll
            for (int c = 0; c < 4; ++c) acc[i][j][c] = 0.f;

    // per-thread chunk plan: 8 A chunks + 2 B chunks
    const char* gp[10];
    uint32_t    so[10];
    int         step[10];
    #pragma unroll
    for (int j = 0; j < 10; ++j) {
        int idx = j * 128 + t;
        if (idx < 1024) {                           // A: 128 rows x 8 seg
            int row = idx >> 3, seg = idx & 7;
            so[j]   = (uint32_t)(row * A_ROW_B + seg * 16);
            gp[j]   = (const char*)(A + (size_t)(m0 + row) * NROW + k0 + seg * 4);
            step[j] = BK * 4;
        } else {                                    // B: 64 rows x 4 seg
            int q2 = idx - 1024;
            int n = q2 >> 2, seg = q2 & 3;
            so[j]   = (uint32_t)(A_STG_B + n * B_ROW_B + seg * 16);
            gp[j]   = (const char*)(g_Bh + (size_t)n * NROW + k0 + seg * 8);
            step[j] = BK * 2;
        }
    }

    auto load_stage = [&](int st) {
        const uint32_t sb = smb + st * STG_B;
        #pragma unroll
        for (int j = 0; j < 10; ++j) cp_async16(sb + so[j], gp[j]);
        #pragma unroll
        for (int j = 0; j < 10; ++j) gp[j] += step[j];
    };

    #pragma unroll
    for (int p = 0; p < STAGES - 1; ++p) {
        load_stage(p);
        asm volatile("cp.async.commit_group;");
    }

    for (int it = 0; it < NIT; ++it) {
        asm volatile("cp.async.wait_group %0;" :: "n"(STAGES - 2));
        __syncthreads();

        if (it + STAGES - 1 < NIT) load_stage((it + STAGES - 1) & (STAGES - 1));
        asm volatile("cp.async.commit_group;");

        const int st = it & (STAGES - 1);
        const float*  sA = (const float*)(smem + st * STG_B);
        const __half* sB = (const __half*)(smem + st * STG_B + A_STG_B);

        #pragma unroll
        for (int kt = 0; kt < 2; ++kt) {              // two k16 tiles
            const int kb = kt * 16 + 2 * q;
            uint32_t b0[8], b1[8];
            #pragma unroll
            for (int j = 0; j < 8; ++j) {             // banks 20g+q: conflict-free
                const int n = j * 8 + g;
                b0[j] = *(const uint32_t*)&sB[n * 40 + kb];
                b1[j] = *(const uint32_t*)&sB[n * 40 + kb + 8];
            }
            #pragma unroll
            for (int i = 0; i < 2; ++i) {
                const int R = warp * 32 + i * 16;
                float2 p0 = *(const float2*)&sA[(R + g)     * 40 + kb];
                float2 p1 = *(const float2*)&sA[(R + g + 8) * 40 + kb];
                float2 p2 = *(const float2*)&sA[(R + g)     * 40 + kb + 8];
                float2 p3 = *(const float2*)&sA[(R + g + 8) * 40 + kb + 8];
                uint32_t a0 = pack_h2(p0.x, p0.y);
                uint32_t a1 = pack_h2(p1.x, p1.y);
                uint32_t a2 = pack_h2(p2.x, p2.y);
                uint32_t a3 = pack_h2(p3.x, p3.y);
                #pragma unroll
                for (int j = 0; j < 8; ++j)
                    mma_f16(acc[i][j], a0, a1, a2, a3, b0[j], b1[j]);
            }
        }
    }

    float* P = &g_partial[ks][0];
    #pragma unroll
    for (int i = 0; i < 2; ++i) {
        #pragma unroll
        for (int j = 0; j < 8; ++j) {
            const int row = m0 + warp * 32 + i * 16 + g;
            const int col = j * 8 + q * 2;
            *(float2*)(P + (size_t)row * NC + col)       = make_float2(acc[i][j][0], acc[i][j][1]);
            *(float2*)(P + (size_t)(row + 8) * NC + col) = make_float2(acc[i][j][2], acc[i][j][3]);
        }
    }
}

// ---------------------------------------------------------------------------
// Kernel 3: out = sum_ks partial[ks]
// ---------------------------------------------------------------------------
__global__ void __launch_bounds__(256) reduce_k(float* __restrict__ out) {
    const int idx = blockIdx.x * blockDim.x + threadIdx.x;     // float4 index
    float4 s = make_float4(0.f, 0.f, 0.f, 0.f);
    #pragma unroll
    for (int k = 0; k < KSPLIT; ++k) {
        const float4 v = ((const float4*)g_partial[k])[idx];
        s.x += v.x; s.y += v.y; s.z += v.z; s.w += v.w;
    }
    ((float4*)out)[idx] = s;
}

// ---------------------------------------------------------------------------
extern "C" void kernel_launch(void* const* d_in, const int* in_sizes, int n_in,
                              void* d_out, int out_size) {
    const float* x   = (const float*)d_in[0];   // [16384, 64]
    const float* adj = (const float*)d_in[1];   // [16384, 16384]
    const float* w   = (const float*)d_in[2];   // [64, 64]
    float* out = (float*)d_out;

    cudaFuncSetAttribute(gcn_main, cudaFuncAttributeMaxDynamicSharedMemorySize, MAIN_SMEM);

    xw_t<<<NROW / 64, 256>>>(x, w);
    gcn_main<<<128 * KSPLIT, 128, MAIN_SMEM>>>(adj);
    reduce_k<<<(NROW * NC / 4) / 256, 256>>>(out);
}

// round 7
// speedup vs baseline: 1.7405x; 1.1047x over previous
#include <cuda_runtime.h>
#include <cuda_fp16.h>
#include <cstdint>

#define NROW 16384
#define NC   64
#define BM   128
#define BK   64
#define NIT  (NROW / BK)              /* 256 */
#define STAGES 3

#define A_ROW_B 288                   /* 72 floats: 64 data + 8 pad  */
#define B_ROW_B 144                   /* 72 halves: 64 data + 8 pad  */
#define A_STG_B (BM * A_ROW_B)        /* 36864 */
#define B_STG_B (NC * B_ROW_B)        /*  9216 */
#define STG_B   (A_STG_B + B_STG_B)   /* 46080 */
#define MAIN_SMEM (STAGES * STG_B)    /* 138240 */

__device__ __half g_Bh[(size_t)NC * NROW];   // (x@w)^T in fp16, K-major, 2 MiB

// ---------------------------------------------------------------------------
__device__ __forceinline__ uint32_t smem_u32(const void* p) {
    uint32_t a;
    asm("{ .reg .u64 t; cvta.to.shared.u64 t, %1; cvt.u32.u64 %0, t; }" : "=r"(a) : "l"(p));
    return a;
}
__device__ __forceinline__ void cp_async16(uint32_t saddr, const void* g) {
    asm volatile("cp.async.cg.shared.global [%0], [%1], 16;" :: "r"(saddr), "l"(g));
}
__device__ __forceinline__ uint32_t pack_h2(float lo, float hi) {
    uint32_t r;
    asm("cvt.rn.f16x2.f32 %0, %1, %2;" : "=r"(r) : "f"(hi), "f"(lo));
    return r;
}
__device__ __forceinline__ void mma_f16(float c[4], uint32_t a0, uint32_t a1,
                                        uint32_t a2, uint32_t a3,
                                        uint32_t b0, uint32_t b1) {
    asm volatile(
        "mma.sync.aligned.m16n8k16.row.col.f32.f16.f16.f32 "
        "{%0,%1,%2,%3},{%4,%5,%6,%7},{%8,%9},{%0,%1,%2,%3};"
        : "+f"(c[0]), "+f"(c[1]), "+f"(c[2]), "+f"(c[3])
        : "r"(a0), "r"(a1), "r"(a2), "r"(a3), "r"(b0), "r"(b1));
}

// ---------------------------------------------------------------------------
// Kernel 1: g_Bh[n][k] = fp16( sum_c x[k][c] * w[c][n] )
// ---------------------------------------------------------------------------
__global__ void __launch_bounds__(256) xw_t(const float* __restrict__ x,
                                            const float* __restrict__ w) {
    __shared__ float ws[NC * NC];
    __shared__ float xs[64 * 65];
    __shared__ __half ts[NC * 72];
    const int t  = threadIdx.x;
    const int k0 = blockIdx.x * 64;

    #pragma unroll
    for (int j = 0; j < 4; ++j) ((float4*)ws)[j * 256 + t] = ((const float4*)w)[j * 256 + t];
    #pragma unroll
    for (int j = 0; j < 4; ++j) {
        int i4 = j * 256 + t;
        int r = i4 >> 4, c4 = i4 & 15;
        float4 v = ((const float4*)(x + (size_t)(k0 + r) * NC))[c4];
        float* d = xs + r * 65 + c4 * 4;
        d[0] = v.x; d[1] = v.y; d[2] = v.z; d[3] = v.w;
    }
    __syncthreads();

    const int r  = t & 63;
    const int n0 = (t >> 6) * 16;
    float acc[16];
    #pragma unroll
    for (int j = 0; j < 16; ++j) acc[j] = 0.f;
    #pragma unroll 4
    for (int c = 0; c < NC; ++c) {
        const float xv = xs[r * 65 + c];
        #pragma unroll
        for (int j4 = 0; j4 < 4; ++j4) {
            float4 wv = *(const float4*)&ws[c * NC + n0 + j4 * 4];
            acc[j4 * 4 + 0] += xv * wv.x;
            acc[j4 * 4 + 1] += xv * wv.y;
            acc[j4 * 4 + 2] += xv * wv.z;
            acc[j4 * 4 + 3] += xv * wv.w;
        }
    }
    #pragma unroll
    for (int j = 0; j < 16; ++j) ts[(n0 + j) * 72 + r] = __float2half_rn(acc[j]);
    __syncthreads();

    #pragma unroll
    for (int i = 0; i < 2; ++i) {
        int i4 = i * 256 + t;
        int n = i4 >> 3, c8 = i4 & 7;
        uint4 v = *(const uint4*)&ts[n * 72 + c8 * 8];
        *(uint4*)(g_Bh + (size_t)n * NROW + k0 + c8 * 8) = v;
    }
}

// ---------------------------------------------------------------------------
// Kernel 2: out[m0:m0+128, :] = adj[m0:m0+128, :] @ B    (full K, no split)
// fp16 mma.sync m16n8k16, BK=64, 3-stage cp.async pipeline, 1 CTA/SM
// ---------------------------------------------------------------------------
__global__ void __launch_bounds__(128, 1) gcn_main(const float* __restrict__ A,
                                                   float* __restrict__ out) {
    extern __shared__ char smem[];
    const uint32_t smb = smem_u32(smem);

    const int t    = threadIdx.x;
    const int m0   = blockIdx.x * BM;
    const int warp = t >> 5, lane = t & 31;
    const int g    = lane >> 2;            // 0..7
    const int q    = lane & 3;             // 0..3

    float acc[2][8][4];
    #pragma unroll
    for (int i = 0; i < 2; ++i)
        #pragma unroll
        for (int j = 0; j < 8; ++j)
            #pragma unroll
            for (int c = 0; c < 4; ++c) acc[i][j][c] = 0.f;

    // per-thread load plan:
    //   A: 16 chunks, chunk j -> row (j*8 + t>>4), seg (t&15); strides 524288B g / 2304B s
    //   B:  4 chunks, chunk j -> n   (j*16 + t>>3), seg (t&7) ; strides 524288B g / 2304B s
    const int ar = t >> 4, as = t & 15;
    const int bn = t >> 3, bs = t & 7;
    const char* gA = (const char*)A + ((size_t)(m0 + ar) * NROW + (size_t)as * 4) * 4;
    const char* gB = (const char*)g_Bh + ((size_t)bn * NROW + (size_t)bs * 8) * 2;
    const uint32_t sAo = (uint32_t)(ar * A_ROW_B + as * 16);
    const uint32_t sBo = (uint32_t)(A_STG_B + bn * B_ROW_B + bs * 16);

    auto load_stage = [&](int st) {
        const uint32_t sb = smb + st * STG_B;
        #pragma unroll
        for (int j = 0; j < 16; ++j)
            cp_async16(sb + sAo + j * 2304u, gA + (size_t)j * 524288);
        #pragma unroll
        for (int j = 0; j < 4; ++j)
            cp_async16(sb + sBo + j * 2304u, gB + (size_t)j * 524288);
        gA += BK * 4;
        gB += BK * 2;
    };

    load_stage(0);
    asm volatile("cp.async.commit_group;");
    load_stage(1);
    asm volatile("cp.async.commit_group;");

    int st = 0;
    for (int it = 0; it < NIT; ++it) {
        asm volatile("cp.async.wait_group 1;");
        __syncthreads();

        if (it + 2 < NIT) {
            int nx = st + 2; if (nx >= STAGES) nx -= STAGES;
            load_stage(nx);
        }
        asm volatile("cp.async.commit_group;");

        const float*  sA = (const float*)(smem + st * STG_B);
        const __half* sB = (const __half*)(smem + st * STG_B + A_STG_B);

        #pragma unroll
        for (int kt = 0; kt < 4; ++kt) {            // four k16 tiles
            const int kb = kt * 16 + 2 * q;
            uint32_t b0[8], b1[8];
            #pragma unroll
            for (int j = 0; j < 8; ++j) {           // banks (4g+q): conflict-free
                const int n = j * 8 + g;
                b0[j] = *(const uint32_t*)&sB[n * 72 + kb];
                b1[j] = *(const uint32_t*)&sB[n * 72 + kb + 8];
            }
            #pragma unroll
            for (int i = 0; i < 2; ++i) {
                const int R = warp * 32 + i * 16;
                float2 p0 = *(const float2*)&sA[(R + g)     * 72 + kb];
                float2 p1 = *(const float2*)&sA[(R + g + 8) * 72 + kb];
                float2 p2 = *(const float2*)&sA[(R + g)     * 72 + kb + 8];
                float2 p3 = *(const float2*)&sA[(R + g + 8) * 72 + kb + 8];
                uint32_t a0 = pack_h2(p0.x, p0.y);
                uint32_t a1 = pack_h2(p1.x, p1.y);
                uint32_t a2 = pack_h2(p2.x, p2.y);
                uint32_t a3 = pack_h2(p3.x, p3.y);
                #pragma unroll
                for (int j = 0; j < 8; ++j)
                    mma_f16(acc[i][j], a0, a1, a2, a3, b0[j], b1[j]);
            }
        }
        if (++st == STAGES) st = 0;
    }

    // epilogue: direct write to out
    #pragma unroll
    for (int i = 0; i < 2; ++i) {
        #pragma unroll
        for (int j = 0; j < 8; ++j) {
            const int row = m0 + warp * 32 + i * 16 + g;
            const int col = j * 8 + q * 2;
            *(float2*)(out + (size_t)row * NC + col)       = make_float2(acc[i][j][0], acc[i][j][1]);
            *(float2*)(out + (size_t)(row + 8) * NC + col) = make_float2(acc[i][j][2], acc[i][j][3]);
        }
    }
}

// ---------------------------------------------------------------------------
extern "C" void kernel_launch(void* const* d_in, const int* in_sizes, int n_in,
                              void* d_out, int out_size) {
    const float* x   = (const float*)d_in[0];   // [16384, 64]
    const float* adj = (const float*)d_in[1];   // [16384, 16384]
    const float* w   = (const float*)d_in[2];   // [64, 64]
    float* out = (float*)d_out;

    cudaFuncSetAttribute(gcn_main, cudaFuncAttributeMaxDynamicSharedMemorySize, MAIN_SMEM);

    xw_t<<<NROW / 64, 256>>>(x, w);
    gcn_main<<<NROW / BM, 128, MAIN_SMEM>>>(adj, out);
}